// round 4
// baseline (speedup 1.0000x reference)
#include <cuda_runtime.h>
#include <math.h>

#define BB 64
#define CC 32
#define LL 6400
#define NH 8
#define INV_PI 0.318309886183790671538f

typedef unsigned long long ull;

// ---------------- f32x2 packed-math helpers ----------------
__device__ __forceinline__ ull pack2(float lo, float hi){
    ull r; asm("mov.b64 %0,{%1,%2};" : "=l"(r) : "f"(lo), "f"(hi)); return r;
}
__device__ __forceinline__ void fma2(ull& d, ull a, ull b){
    asm("fma.rn.f32x2 %0,%1,%2,%0;" : "+l"(d) : "l"(a), "l"(b));
}
__device__ __forceinline__ float hsum2(ull v){
    float lo, hi; asm("mov.b64 {%0,%1},%2;" : "=f"(lo), "=f"(hi) : "l"(v)); return lo + hi;
}
__device__ __forceinline__ float dot16(const ull* wrow, const ull* xp){
    ull a0 = 0ULL, a1 = 0ULL;
    #pragma unroll
    for(int cc=0; cc<16; cc+=2){ fma2(a0, wrow[cc], xp[cc]); fma2(a1, wrow[cc+1], xp[cc+1]); }
    return hsum2(a0) + hsum2(a1);
}
// two pixels sharing one weight-row load
__device__ __forceinline__ void dot16_dual(const ull* wrow, const ull* x0, const ull* x1,
                                           float& r0, float& r1){
    ull a0=0ULL,a1=0ULL,b0=0ULL,b1=0ULL;
    #pragma unroll
    for(int cc=0;cc<16;cc+=2){
        ull w0=wrow[cc], w1=wrow[cc+1];
        fma2(a0,w0,x0[cc]); fma2(a1,w1,x0[cc+1]);
        fma2(b0,w0,x1[cc]); fma2(b1,w1,x1[cc+1]);
    }
    r0 = hsum2(a0)+hsum2(a1);
    r1 = hsum2(b0)+hsum2(b1);
}
__device__ __forceinline__ float wsum(float v){
    #pragma unroll
    for(int o=16;o>0;o>>=1) v += __shfl_xor_sync(0xffffffffu, v, o);
    return v;
}
__device__ __forceinline__ float wmax(float v){
    #pragma unroll
    for(int o=16;o>0;o>>=1) v = fmaxf(v, __shfl_xor_sync(0xffffffffu, v, o));
    return v;
}

// ---------------- scratch ----------------
__device__ float g_f1[BB*CC*LL];
__device__ float g_f2[BB*CC*LL];
__device__ float g_part1[BB*25*128];
__device__ float g_part2[BB*25*192];
__device__ float g_attn1[BB*NH*16];
__device__ float g_attn2[BB*NH*16];
__device__ float g_poolp[2][BB*50][64];  // [stream][block][c=sum | 32+c=max]
__device__ float g_avg[2*BB*CC];
__device__ float g_mx[2*BB*CC];
__device__ float g_w1[BB*CC*CC];
__device__ float g_w2[BB*CC*CC];
__device__ float g_pool[4*BB*LL];
__device__ float g_gate[BB*2*LL];

// ---------------- K1: lin phase1 — compute k,v; block-partial outer(kn,v) ----------------
__global__ __launch_bounds__(128) void lin_p1_kernel(const float* __restrict__ x,
                                                     const float* __restrict__ w){
    __shared__ ull sw[1024];               // k rows (0..511), v rows (512..1023)
    __shared__ float wp[4][8][16];
    int tid = threadIdx.x, b = blockIdx.y;
    const ull* wg = (const ull*)w;
    for(int i=tid;i<1024;i+=128) sw[i] = wg[512+i];   // rows 32..95
    __syncthreads();
    int base = blockIdx.x*256;
    int l0 = base+tid, l1 = base+128+tid;
    const float* xb = x + b*CC*LL;
    ull xp0[16], xp1[16];
    #pragma unroll
    for(int c=0;c<16;c++){
        xp0[c]=pack2(xb[(2*c)*LL+l0], xb[(2*c+1)*LL+l0]);
        xp1[c]=pack2(xb[(2*c)*LL+l1], xb[(2*c+1)*LL+l1]);
    }
    int lane = tid&31, wid = tid>>5;
    #pragma unroll
    for(int h=0;h<8;h++){
        float k0[4],k1[4],v0[4],v1[4];
        #pragma unroll
        for(int d=0;d<4;d++) dot16_dual(sw + (h*4+d)*16, xp0, xp1, k0[d], k1[d]);
        #pragma unroll
        for(int d=0;d<4;d++) dot16_dual(sw + 512 + (h*4+d)*16, xp0, xp1, v0[d], v1[d]);
        float ik0 = rsqrtf(k0[0]*k0[0]+k0[1]*k0[1]+k0[2]*k0[2]+k0[3]*k0[3]);
        float ik1 = rsqrtf(k1[0]*k1[0]+k1[1]*k1[1]+k1[2]*k1[2]+k1[3]*k1[3]);
        #pragma unroll
        for(int d=0;d<4;d++){ k0[d]*=ik0; k1[d]*=ik1; }
        #pragma unroll
        for(int d=0;d<4;d++)
            #pragma unroll
            for(int e=0;e<4;e++){
                float p = k0[d]*v0[e] + k1[d]*v1[e];
                p = wsum(p);
                if(lane==0) wp[wid][h][d*4+e]=p;
            }
    }
    __syncthreads();
    float s = wp[0][tid>>4][tid&15] + wp[1][tid>>4][tid&15]
            + wp[2][tid>>4][tid&15] + wp[3][tid>>4][tid&15];
    g_part1[(b*25+blockIdx.x)*128 + tid] = s;
}

__global__ __launch_bounds__(128) void lin_red_kernel(){
    int b = blockIdx.x, t = threadIdx.x;
    float s = 0.f;
    #pragma unroll
    for(int i=0;i<25;i++) s += g_part1[(b*25+i)*128 + t];
    g_attn1[b*128+t] = INV_PI*s;
}

// ---------------- K2: xca phase1 — compute q,k; block-partial gram + norms ----------------
__global__ __launch_bounds__(128) void xca_p1_kernel(const float* __restrict__ x,
                                                     const float* __restrict__ w){
    __shared__ ull sw[1024];               // q rows (0..511), k rows (512..1023)
    __shared__ float wp[4][8][24];
    int tid = threadIdx.x, b = blockIdx.y;
    const ull* wg = (const ull*)w;
    for(int i=tid;i<1024;i+=128) sw[i] = wg[i];       // rows 0..63
    __syncthreads();
    int base = blockIdx.x*256;
    int l0 = base+tid, l1 = base+128+tid;
    const float* xb = x + b*CC*LL;
    ull xp0[16], xp1[16];
    #pragma unroll
    for(int c=0;c<16;c++){
        xp0[c]=pack2(xb[(2*c)*LL+l0], xb[(2*c+1)*LL+l0]);
        xp1[c]=pack2(xb[(2*c)*LL+l1], xb[(2*c+1)*LL+l1]);
    }
    int lane = tid&31, wid = tid>>5;
    #pragma unroll
    for(int h=0;h<8;h++){
        float q0[4],q1[4],k0[4],k1[4];
        #pragma unroll
        for(int d=0;d<4;d++) dot16_dual(sw + (h*4+d)*16, xp0, xp1, q0[d], q1[d]);
        #pragma unroll
        for(int d=0;d<4;d++) dot16_dual(sw + 512 + (h*4+d)*16, xp0, xp1, k0[d], k1[d]);
        #pragma unroll
        for(int d=0;d<4;d++)
            #pragma unroll
            for(int e=0;e<4;e++){
                float p = q0[d]*k0[e] + q1[d]*k1[e];
                p = wsum(p);
                if(lane==0) wp[wid][h][d*4+e]=p;
            }
        #pragma unroll
        for(int d=0;d<4;d++){
            float p = q0[d]*q0[d] + q1[d]*q1[d];
            p = wsum(p);
            if(lane==0) wp[wid][h][16+d]=p;
        }
        #pragma unroll
        for(int d=0;d<4;d++){
            float p = k0[d]*k0[d] + k1[d]*k1[d];
            p = wsum(p);
            if(lane==0) wp[wid][h][20+d]=p;
        }
    }
    __syncthreads();
    for(int t=tid; t<192; t+=128){
        int h = t/24, i = t%24;
        float s = wp[0][h][i]+wp[1][h][i]+wp[2][h][i]+wp[3][h][i];
        g_part2[(b*25+blockIdx.x)*192 + t] = s;
    }
}

__global__ __launch_bounds__(256) void xca_red_kernel(const float* __restrict__ temp){
    __shared__ float red[192];
    int b = blockIdx.x, t = threadIdx.x;
    if(t<192){
        float s=0.f;
        #pragma unroll
        for(int i=0;i<25;i++) s += g_part2[(b*25+i)*192 + t];
        red[t]=s;
    }
    __syncthreads();
    if(t<32){
        int h = t>>2, d = t&3;
        int base = h*24;
        float qn = fmaxf(sqrtf(red[base+16+d]), 1e-12f);
        float tt = temp[h];
        float vals[4]; float m = -3.4e38f;
        #pragma unroll
        for(int e=0;e<4;e++){
            float kn = fmaxf(sqrtf(red[base+20+e]), 1e-12f);
            vals[e] = red[base+d*4+e] / (qn*kn) * tt;
            m = fmaxf(m, vals[e]);
        }
        float s=0.f;
        #pragma unroll
        for(int e=0;e<4;e++){ vals[e]=expf(vals[e]-m); s+=vals[e]; }
        float inv = 1.f/s;
        #pragma unroll
        for(int e=0;e<4;e++) g_attn2[b*128 + h*16 + d*4 + e] = vals[e]*inv;
    }
}

// ---------------- K3: lin output — recompute q,v; 0.5v+q@attn, norm, dconv, proj; pool partial ----------------
__global__ __launch_bounds__(128) void lin_out_kernel(const float* __restrict__ x,
                                                      const float* __restrict__ qkvw,
                                                      const float* __restrict__ dconv_w,
                                                      const float* __restrict__ projw,
                                                      const float* __restrict__ projb){
    __shared__ ull sqw[512];     // q rows 0..31
    __shared__ ull svw[512];     // v rows 64..95
    __shared__ ull pw[512];
    __shared__ float w9s[72], pbs[32], attnS[128];
    __shared__ float s_v[32][136];
    __shared__ float s_ps[4][32], s_pm[4][32];
    int tid = threadIdx.x, b = blockIdx.y;
    const ull* wg = (const ull*)qkvw;
    const ull* pg = (const ull*)projw;
    for(int i=tid;i<512;i+=128){ sqw[i]=wg[i]; svw[i]=wg[1024+i]; pw[i]=pg[i]; }
    if(tid<72) w9s[tid]=dconv_w[tid];
    if(tid<32) pbs[tid]=projb[tid];
    attnS[tid] = g_attn1[b*128+tid];
    __syncthreads();
    int base = blockIdx.x*128;
    int l = base + tid;
    const float* xb = x + b*CC*LL;
    ull xp[16];
    #pragma unroll
    for(int c=0;c<16;c++) xp[c]=pack2(xb[(2*c)*LL+l], xb[(2*c+1)*LL+l]);
    float q[32];
    #pragma unroll
    for(int j=0;j<32;j++) q[j] = dot16(sqw+j*16, xp);
    // FIX: per-head L2 normalization of q (reference: q / ||q||, per pixel per head)
    #pragma unroll
    for(int h=0;h<8;h++){
        float sq = q[h*4]*q[h*4] + q[h*4+1]*q[h*4+1] + q[h*4+2]*q[h*4+2] + q[h*4+3]*q[h*4+3];
        float iq = rsqrtf(sq);
        #pragma unroll
        for(int d=0;d<4;d++) q[h*4+d] *= iq;
    }
    #pragma unroll
    for(int j=0;j<32;j++) s_v[j][4+tid] = dot16(svw+j*16, xp);
    // halo v (4 left, 4 right), recomputed from x
    if(tid<8){
        int col = (tid<4) ? tid : (128+tid);          // 0..3 and 132..135
        int hl  = (tid<4) ? (base-4+tid) : (base+128+(tid-4));
        if(hl>=0 && hl<LL){
            ull xph[16];
            #pragma unroll
            for(int c=0;c<16;c++) xph[c]=pack2(xb[(2*c)*LL+hl], xb[(2*c+1)*LL+hl]);
            #pragma unroll
            for(int j=0;j<32;j++) s_v[j][col] = dot16(svw+j*16, xph);
        } else {
            #pragma unroll
            for(int j=0;j<32;j++) s_v[j][col] = 0.f;
        }
    }
    __syncthreads();
    float o[32];
    #pragma unroll
    for(int h=0;h<8;h++){
        float vv[4];
        #pragma unroll
        for(int d=0;d<4;d++) vv[d]=s_v[h*4+d][4+tid];
        float ov[4]; float s=0.f;
        #pragma unroll
        for(int e=0;e<4;e++){
            float t = 0.5f*vv[e];
            #pragma unroll
            for(int d=0;d<4;d++) t += q[h*4+d]*attnS[h*16+d*4+e];
            ov[e]=t; s+=t*t;
        }
        float inv = rsqrtf(s);
        #pragma unroll
        for(int d=0;d<4;d++){
            float acc = 0.f;
            #pragma unroll
            for(int t9=0;t9<9;t9++) acc += w9s[h*9+t9]*s_v[h*4+d][tid+t9];
            o[h*4+d] = ov[d]*inv + acc;
        }
    }
    ull op[16];
    #pragma unroll
    for(int cc=0;cc<16;cc++) op[cc]=pack2(o[2*cc], o[2*cc+1]);
    float* fb = g_f1 + b*CC*LL + l;
    int lane=tid&31, wid=tid>>5;
    #pragma unroll
    for(int c=0;c<32;c++){
        ull a0=0ULL,a1=0ULL;
        #pragma unroll
        for(int cc=0;cc<16;cc+=2){ fma2(a0,pw[c*16+cc],op[cc]); fma2(a1,pw[c*16+cc+1],op[cc+1]); }
        float f = hsum2(a0)+hsum2(a1)+pbs[c];
        fb[c*LL] = f;
        float ss = wsum(f);
        float mm = wmax(f);
        if(lane==0){ s_ps[wid][c]=ss; s_pm[wid][c]=mm; }
    }
    __syncthreads();
    if(tid<32){
        int blk = b*50 + blockIdx.x;
        g_poolp[0][blk][tid]    = s_ps[0][tid]+s_ps[1][tid]+s_ps[2][tid]+s_ps[3][tid];
        g_poolp[0][blk][32+tid] = fmaxf(fmaxf(s_pm[0][tid],s_pm[1][tid]),fmaxf(s_pm[2][tid],s_pm[3][tid]));
    }
}

// ---------------- K4: xca output — recompute v; attn@v, proj; pool partial ----------------
__global__ __launch_bounds__(128) void xca_out_kernel(const float* __restrict__ x,
                                                      const float* __restrict__ qkvw,
                                                      const float* __restrict__ projw,
                                                      const float* __restrict__ projb){
    __shared__ ull svw[512];
    __shared__ ull pw[512];
    __shared__ float pbs[32], attnS[128];
    __shared__ float s_ps[4][32], s_pm[4][32];
    int tid = threadIdx.x, b = blockIdx.y;
    const ull* wg = (const ull*)qkvw;
    const ull* pg = (const ull*)projw;
    for(int i=tid;i<512;i+=128){ svw[i]=wg[1024+i]; pw[i]=pg[i]; }
    if(tid<32) pbs[tid]=projb[tid];
    attnS[tid] = g_attn2[b*128+tid];
    __syncthreads();
    int l = blockIdx.x*128 + tid;
    const float* xb = x + b*CC*LL;
    ull xp[16];
    #pragma unroll
    for(int c=0;c<16;c++) xp[c]=pack2(xb[(2*c)*LL+l], xb[(2*c+1)*LL+l]);
    float o[32];
    #pragma unroll
    for(int h=0;h<8;h++){
        float vv[4];
        #pragma unroll
        for(int e=0;e<4;e++) vv[e] = dot16(svw+(h*4+e)*16, xp);
        #pragma unroll
        for(int d=0;d<4;d++){
            float t = 0.f;
            #pragma unroll
            for(int e=0;e<4;e++) t += attnS[h*16+d*4+e]*vv[e];
            o[h*4+d]=t;
        }
    }
    ull op[16];
    #pragma unroll
    for(int cc=0;cc<16;cc++) op[cc]=pack2(o[2*cc], o[2*cc+1]);
    float* fb = g_f2 + b*CC*LL + l;
    int lane=tid&31, wid=tid>>5;
    #pragma unroll
    for(int c=0;c<32;c++){
        ull a0=0ULL,a1=0ULL;
        #pragma unroll
        for(int cc=0;cc<16;cc+=2){ fma2(a0,pw[c*16+cc],op[cc]); fma2(a1,pw[c*16+cc+1],op[cc+1]); }
        float f = hsum2(a0)+hsum2(a1)+pbs[c];
        fb[c*LL] = f;
        float ss = wsum(f);
        float mm = wmax(f);
        if(lane==0){ s_ps[wid][c]=ss; s_pm[wid][c]=mm; }
    }
    __syncthreads();
    if(tid<32){
        int blk = b*50 + blockIdx.x;
        g_poolp[1][blk][tid]    = s_ps[0][tid]+s_ps[1][tid]+s_ps[2][tid]+s_ps[3][tid];
        g_poolp[1][blk][32+tid] = fmaxf(fmaxf(s_pm[0][tid],s_pm[1][tid]),fmaxf(s_pm[2][tid],s_pm[3][tid]));
    }
}

// ---------------- K5: pool reduce ----------------
__global__ __launch_bounds__(64) void pool_red_kernel(){
    int s = blockIdx.x>>6, b = blockIdx.x&63;
    int t = threadIdx.x;
    if(t<32){
        float acc = 0.f;
        #pragma unroll
        for(int i=0;i<50;i++) acc += g_poolp[s][b*50+i][t];
        g_avg[s*BB*CC + b*32 + t] = acc;
    } else {
        int c = t-32;
        float m = -3.4e38f;
        #pragma unroll
        for(int i=0;i<50;i++) m = fmaxf(m, g_poolp[s][b*50+i][32+c]);
        g_mx[s*BB*CC + b*32 + c] = m;
    }
}

// ---------------- K6: CAFM channel MLPs + cross softmax weights ----------------
__global__ __launch_bounds__(64) void cafm_kernel(
    const float* __restrict__ aw1,  const float* __restrict__ ab1,
    const float* __restrict__ mw1,  const float* __restrict__ mb1,
    const float* __restrict__ aw2,  const float* __restrict__ ab2,
    const float* __restrict__ mw2,  const float* __restrict__ mb2,
    const float* __restrict__ aw11, const float* __restrict__ ab11,
    const float* __restrict__ mw11, const float* __restrict__ mb11,
    const float* __restrict__ aw22, const float* __restrict__ ab22,
    const float* __restrict__ mw22, const float* __restrict__ mb22){
    int b = blockIdx.x, t = threadIdx.x;
    __shared__ float sa[4][32], hid[4][16], a1s[32], a2s[32];
    if(t<32){
        sa[0][t] = g_avg[b*32+t] * (1.0f/LL);
        sa[1][t] = g_mx[b*32+t];
        sa[2][t] = g_avg[BB*CC + b*32+t] * (1.0f/LL);
        sa[3][t] = g_mx[BB*CC + b*32+t];
    }
    __syncthreads();
    {
        int br = t>>4, hh = t&15;
        const float* w  = (br==0)?aw1 : (br==1)?mw1 : (br==2)?aw2 : mw2;
        const float* bi = (br==0)?ab1 : (br==1)?mb1 : (br==2)?ab2 : mb2;
        float s = bi[hh];
        #pragma unroll
        for(int c=0;c<32;c++) s += sa[br][c]*w[hh*32+c];
        hid[br][hh] = fmaxf(s, 0.f);
    }
    __syncthreads();
    if(t<32){
        float s = ab11[t] + mb11[t];
        #pragma unroll
        for(int h=0;h<16;h++) s += hid[0][h]*aw11[t*16+h] + hid[1][h]*mw11[t*16+h];
        a1s[t]=s;
    } else {
        int c = t-32;
        float s = ab22[c] + mb22[c];
        #pragma unroll
        for(int h=0;h<16;h++) s += hid[2][h]*aw22[c*16+h] + hid[3][h]*mw22[c*16+h];
        a2s[c]=s;
    }
    __syncthreads();
    if(t<32){
        float a = a1s[t];
        float e[32]; float m = -3.4e38f;
        #pragma unroll
        for(int d=0;d<32;d++){ e[d]=a*a2s[d]; m=fmaxf(m,e[d]); }
        float s=0.f;
        #pragma unroll
        for(int d=0;d<32;d++){ e[d]=expf(e[d]-m); s+=e[d]; }
        float inv = 1.f/s;
        #pragma unroll
        for(int d=0;d<32;d++) g_w1[b*1024 + t*32 + d] = e[d]*inv;
    } else {
        int c = t-32;
        float a = a2s[c];
        float e[32]; float m = -3.4e38f;
        #pragma unroll
        for(int d=0;d<32;d++){ e[d]=a*a1s[d]; m=fmaxf(m,e[d]); }
        float s=0.f;
        #pragma unroll
        for(int d=0;d<32;d++){ e[d]=expf(e[d]-m); s+=e[d]; }
        float inv = 1.f/s;
        #pragma unroll
        for(int d=0;d<32;d++) g_w2[b*1024 + c*32 + d] = e[d]*inv;
    }
}

// ---------------- K7: a1f/a2f matvec + channel mean/max -> g_pool ----------------
__global__ __launch_bounds__(128) void a1f_pool_kernel(){
    __shared__ ull w1s[512], w2s[512];
    int tid = threadIdx.x, b = blockIdx.y;
    const ull* w1g = (const ull*)(g_w1 + b*1024);
    const ull* w2g = (const ull*)(g_w2 + b*1024);
    for(int i=tid;i<512;i+=128){ w1s[i]=w1g[i]; w2s[i]=w2g[i]; }
    __syncthreads();
    int l = blockIdx.x*128 + tid;
    const float* f1b = g_f1 + b*CC*LL + l;
    const float* f2b = g_f2 + b*CC*LL + l;
    ull f1p[16], f2p[16];
    #pragma unroll
    for(int cc=0;cc<16;cc++){
        f1p[cc] = pack2(f1b[(2*cc)*LL], f1b[(2*cc+1)*LL]);
        f2p[cc] = pack2(f2b[(2*cc)*LL], f2b[(2*cc+1)*LL]);
    }
    float s1=0.f, m1=-3.4e38f, s2=0.f, m2=-3.4e38f;
    #pragma unroll
    for(int c=0;c<32;c++){
        ull a0=0ULL,a1=0ULL,b0=0ULL,b1=0ULL;
        #pragma unroll
        for(int cc=0;cc<16;cc+=2){
            fma2(a0,w1s[c*16+cc],f1p[cc]);   fma2(a1,w1s[c*16+cc+1],f1p[cc+1]);
            fma2(b0,w2s[c*16+cc],f2p[cc]);   fma2(b1,w2s[c*16+cc+1],f2p[cc+1]);
        }
        float v1 = hsum2(a0)+hsum2(a1);
        float v2 = hsum2(b0)+hsum2(b1);
        s1+=v1; m1=fmaxf(m1,v1);
        s2+=v2; m2=fmaxf(m2,v2);
    }
    g_pool[(0*BB+b)*LL + l] = s1*(1.f/32.f);
    g_pool[(1*BB+b)*LL + l] = m1;
    g_pool[(2*BB+b)*LL + l] = s2*(1.f/32.f);
    g_pool[(3*BB+b)*LL + l] = m2;
}

// ---------------- K8: spatial gate ----------------
__global__ __launch_bounds__(256) void gate_kernel(const float* __restrict__ c1w,
                                                   const float* __restrict__ c1b,
                                                   const float* __restrict__ c2w,
                                                   const float* __restrict__ c2b){
    __shared__ float y1[LL];
    __shared__ float red[8];
    int t = threadIdx.x;
    int b = blockIdx.x>>1, s = blockIdx.x&1;
    const float* pm = g_pool + ((s*2+0)*BB + b)*LL;
    const float* px = g_pool + ((s*2+1)*BB + b)*LL;
    float w1c[18];
    #pragma unroll
    for(int i=0;i<18;i++) w1c[i]=c1w[i];
    float b1 = c1b[0];
    for(int l=t; l<LL; l+=256){
        int iy = l/80, ix = l%80;
        float acc = b1;
        #pragma unroll
        for(int ky=0;ky<3;ky++){
            int yy = iy+ky-1; if(yy<0||yy>=80) continue;
            #pragma unroll
            for(int kx=0;kx<3;kx++){
                int xx = ix+kx-1; if(xx<0||xx>=80) continue;
                int p = yy*80+xx;
                acc += w1c[ky*3+kx]*pm[p] + w1c[9+ky*3+kx]*px[p];
            }
        }
        y1[l] = fmaxf(acc, 0.f);
    }
    __syncthreads();
    float w2c[9];
    #pragma unroll
    for(int i=0;i<9;i++) w2c[i]=c2w[i];
    float b2 = c2b[0];
    float r[25]; float mx = -3.4e38f;
    #pragma unroll
    for(int i=0;i<25;i++){
        int l = t + i*256;
        int iy = l/80, ix = l%80;
        float acc = b2;
        #pragma unroll
        for(int ky=0;ky<3;ky++){
            int yy = iy+ky-1; if(yy<0||yy>=80) continue;
            #pragma unroll
            for(int kx=0;kx<3;kx++){
                int xx = ix+kx-1; if(xx<0||xx>=80) continue;
                acc += w2c[ky*3+kx]*y1[yy*80+xx];
            }
        }
        r[i]=acc; mx=fmaxf(mx,acc);
    }
    int lane = t&31, wid = t>>5;
    #pragma unroll
    for(int o=16;o>0;o>>=1) mx = fmaxf(mx, __shfl_xor_sync(0xffffffffu,mx,o));
    if(lane==0) red[wid]=mx;
    __syncthreads();
    if(t==0){ float m=red[0]; for(int w=1;w<8;w++) m=fmaxf(m,red[w]); red[0]=m; }
    __syncthreads();
    float m = red[0];
    __syncthreads();
    float sm = 0.f;
    #pragma unroll
    for(int i=0;i<25;i++){ r[i]=expf(r[i]-m); sm+=r[i]; }
    #pragma unroll
    for(int o=16;o>0;o>>=1) sm += __shfl_xor_sync(0xffffffffu,sm,o);
    if(lane==0) red[wid]=sm;
    __syncthreads();
    if(t==0){ float a=0.f; for(int w=0;w<8;w++) a+=red[w]; red[0]=a; }
    __syncthreads();
    float inv = 1.f/red[0];
    #pragma unroll
    for(int i=0;i<25;i++) g_gate[(b*2+s)*LL + t + i*256] = r[i]*inv;
}

// ---------------- K9: out = f1*(1+g1) + f2*(1+g2) ----------------
__global__ __launch_bounds__(256) void final_kernel(float* __restrict__ out){
    int i = blockIdx.x*256 + threadIdx.x;
    int idx = i*4;
    int b = idx/(CC*LL);
    int l = idx%LL;
    float4 a  = ((const float4*)g_f1)[i];
    float4 c  = ((const float4*)g_f2)[i];
    float4 g1 = *(const float4*)&g_gate[(b*2+0)*LL + l];
    float4 g2 = *(const float4*)&g_gate[(b*2+1)*LL + l];
    float4 o;
    o.x = a.x*(1.f+g1.x) + c.x*(1.f+g2.x);
    o.y = a.y*(1.f+g1.y) + c.y*(1.f+g2.y);
    o.z = a.z*(1.f+g1.z) + c.z*(1.f+g2.z);
    o.w = a.w*(1.f+g1.w) + c.w*(1.f+g2.w);
    ((float4*)out)[i] = o;
}

// ---------------- launch ----------------
extern "C" void kernel_launch(void* const* d_in, const int* in_sizes, int n_in,
                              void* d_out, int out_size){
    const float* rgb       = (const float*)d_in[0];
    const float* freq      = (const float*)d_in[1];
    const float* la_qkv_w  = (const float*)d_in[2];
    const float* la_proj_w = (const float*)d_in[3];
    const float* la_proj_b = (const float*)d_in[4];
    const float* la_dconv_w= (const float*)d_in[5];
    const float* xa_qkv_w  = (const float*)d_in[6];
    const float* xa_temp   = (const float*)d_in[7];
    const float* xa_proj_w = (const float*)d_in[8];
    const float* xa_proj_b = (const float*)d_in[9];
    const float* c1s_w     = (const float*)d_in[10];
    const float* c1s_b     = (const float*)d_in[11];
    const float* c2s_w     = (const float*)d_in[12];
    const float* c2s_b     = (const float*)d_in[13];

    dim3 g25(25, BB), g50(50, BB);
    lin_p1_kernel<<<g25,128>>>(rgb,  la_qkv_w);
    xca_p1_kernel<<<g25,128>>>(freq, xa_qkv_w);
    lin_red_kernel<<<BB,128>>>();
    xca_red_kernel<<<BB,256>>>(xa_temp);
    lin_out_kernel<<<g50,128>>>(rgb, la_qkv_w, la_dconv_w, la_proj_w, la_proj_b);
    xca_out_kernel<<<g50,128>>>(freq, xa_qkv_w, xa_proj_w, xa_proj_b);
    pool_red_kernel<<<2*BB,64>>>();
    cafm_kernel<<<BB,64>>>((const float*)d_in[14],(const float*)d_in[15],
                           (const float*)d_in[16],(const float*)d_in[17],
                           (const float*)d_in[18],(const float*)d_in[19],
                           (const float*)d_in[20],(const float*)d_in[21],
                           (const float*)d_in[22],(const float*)d_in[23],
                           (const float*)d_in[24],(const float*)d_in[25],
                           (const float*)d_in[26],(const float*)d_in[27],
                           (const float*)d_in[28],(const float*)d_in[29]);
    a1f_pool_kernel<<<g50,128>>>();
    gate_kernel<<<2*BB,256>>>(c1s_w, c1s_b, c2s_w, c2s_b);
    final_kernel<<<(BB*CC*LL/4)/256,256>>>((float*)d_out);
}

// round 5
// speedup vs baseline: 3.2963x; 3.2963x over previous
#include <cuda_runtime.h>
#include <math.h>

#define BB 64
#define CC 32
#define LL 6400
#define NH 8
#define INV_PI 0.318309886183790671538f

typedef unsigned long long ull;

// ---------------- f32x2 packed-math helpers ----------------
__device__ __forceinline__ ull pack2(float lo, float hi){
    ull r; asm("mov.b64 %0,{%1,%2};" : "=l"(r) : "f"(lo), "f"(hi)); return r;
}
__device__ __forceinline__ void fma2(ull& d, ull a, ull b){
    asm("fma.rn.f32x2 %0,%1,%2,%0;" : "+l"(d) : "l"(a), "l"(b));
}
__device__ __forceinline__ float hsum2(ull v){
    float lo, hi; asm("mov.b64 {%0,%1},%2;" : "=f"(lo), "=f"(hi) : "l"(v)); return lo + hi;
}
__device__ __forceinline__ float dot16(const ull* wrow, const ull* xp){
    ull a0 = 0ULL, a1 = 0ULL;
    #pragma unroll
    for(int cc=0; cc<16; cc+=2){ fma2(a0, wrow[cc], xp[cc]); fma2(a1, wrow[cc+1], xp[cc+1]); }
    return hsum2(a0) + hsum2(a1);
}

// ---------------- scratch ----------------
__device__ float g_q1[BB*CC*LL];
__device__ float g_v1[BB*CC*LL];
__device__ float g_v2[BB*CC*LL];
__device__ float g_f1[BB*CC*LL];
__device__ float g_f2[BB*CC*LL];
__device__ float g_part1[BB*50*128];
__device__ float g_part2[BB*50*192];
__device__ float g_attn1[BB*NH*16];
__device__ float g_attn2[BB*NH*16];
__device__ float g_poolp[2][BB*50][64];  // [stream][block][c=sum | 32+c=max]
__device__ float g_avg[2*BB*CC];
__device__ float g_mx[2*BB*CC];
__device__ float g_w1[BB*CC*CC];
__device__ float g_w2[BB*CC*CC];
__device__ float g_pool[4*BB*LL];
__device__ float g_gate[BB*2*LL];

// ---------------- K1: lin qkv — write q(normalized),v; smem-staged kn*v outer partials ----------------
__global__ __launch_bounds__(128) void qkv_lin_kernel(const float* __restrict__ x,
                                                      const float* __restrict__ w){
    __shared__ ull sw[1536];
    __shared__ float skn[32][133];
    __shared__ float sv [32][133];
    int tid = threadIdx.x, b = blockIdx.y;
    const ull* wg = (const ull*)w;
    for(int i=tid; i<1536; i+=128) sw[i] = wg[i];
    __syncthreads();
    int l = blockIdx.x*128 + tid;
    const float* xb = x + b*CC*LL + l;
    ull xp[16];
    #pragma unroll
    for(int c=0;c<16;c++) xp[c] = pack2(xb[(2*c)*LL], xb[(2*c+1)*LL]);
    float* qb = g_q1 + b*CC*LL + l;
    float* vb = g_v1 + b*CC*LL + l;
    #pragma unroll
    for(int h=0;h<NH;h++){
        float qv[4], kv[4], vv[4];
        #pragma unroll
        for(int d=0;d<4;d++){
            int j = h*4+d;
            qv[d] = dot16(sw + j*16,      xp);
            kv[d] = dot16(sw + (32+j)*16, xp);
            vv[d] = dot16(sw + (64+j)*16, xp);
        }
        float iq = rsqrtf(qv[0]*qv[0]+qv[1]*qv[1]+qv[2]*qv[2]+qv[3]*qv[3]);
        float ik = rsqrtf(kv[0]*kv[0]+kv[1]*kv[1]+kv[2]*kv[2]+kv[3]*kv[3]);
        #pragma unroll
        for(int d=0;d<4;d++){
            qb[(h*4+d)*LL] = qv[d]*iq;
            vb[(h*4+d)*LL] = vv[d];
            skn[h*4+d][tid] = kv[d]*ik;
            sv [h*4+d][tid] = vv[d];
        }
    }
    __syncthreads();
    // each thread owns one (h,d,e): sum over this block's 128 pixels
    int h = tid>>4, d = (tid>>2)&3, e = tid&3;
    const float* kr = skn[h*4+d];
    const float* vr = sv [h*4+e];
    float p = 0.f;
    #pragma unroll 8
    for(int i=0;i<128;i++) p += kr[i]*vr[i];
    g_part1[(b*50+blockIdx.x)*128 + tid] = p;
}

__global__ __launch_bounds__(128) void lin_red_kernel(){
    int b = blockIdx.x, t = threadIdx.x;
    float s = 0.f;
    #pragma unroll
    for(int i=0;i<50;i++) s += g_part1[(b*50+i)*128 + t];
    g_attn1[b*128+t] = INV_PI*s;
}

// ---------------- K2: xca qkv — write v only; smem-staged gram+norm partials ----------------
__global__ __launch_bounds__(128) void qkv_xca_kernel(const float* __restrict__ x,
                                                      const float* __restrict__ w){
    __shared__ ull sw[1536];
    __shared__ float sq[32][133];
    __shared__ float sk[32][133];
    int tid = threadIdx.x, b = blockIdx.y;
    const ull* wg = (const ull*)w;
    for(int i=tid; i<1536; i+=128) sw[i] = wg[i];
    __syncthreads();
    int l = blockIdx.x*128 + tid;
    const float* xb = x + b*CC*LL + l;
    ull xp[16];
    #pragma unroll
    for(int c=0;c<16;c++) xp[c] = pack2(xb[(2*c)*LL], xb[(2*c+1)*LL]);
    float* vb = g_v2 + b*CC*LL + l;
    #pragma unroll
    for(int h=0;h<NH;h++){
        #pragma unroll
        for(int d=0;d<4;d++){
            int j = h*4+d;
            sq[j][tid] = dot16(sw + j*16,      xp);
            sk[j][tid] = dot16(sw + (32+j)*16, xp);
            vb[j*LL]   = dot16(sw + (64+j)*16, xp);
        }
    }
    __syncthreads();
    // combos: [0..127] gram h*16+d*4+e ; [128..191] norms h*8 + which*4 + d
    float* pout = &g_part2[(b*50+blockIdx.x)*192];
    {
        int h = tid>>4, d = (tid>>2)&3, e = tid&3;
        const float* qr = sq[h*4+d];
        const float* kr = sk[h*4+e];
        float p = 0.f;
        #pragma unroll 8
        for(int i=0;i<128;i++) p += qr[i]*kr[i];
        pout[tid] = p;
    }
    if(tid < 64){
        int h = tid>>3, which = (tid>>2)&1, d = tid&3;
        const float* r = which ? sk[h*4+d] : sq[h*4+d];
        float p = 0.f;
        #pragma unroll 8
        for(int i=0;i<128;i++) p += r[i]*r[i];
        pout[128 + tid] = p;
    }
}

__global__ __launch_bounds__(256) void xca_red_kernel(const float* __restrict__ temp){
    __shared__ float red[192];
    int b = blockIdx.x, t = threadIdx.x;
    if(t<192){
        float s=0.f;
        #pragma unroll
        for(int i=0;i<50;i++) s += g_part2[(b*50+i)*192 + t];
        red[t]=s;
    }
    __syncthreads();
    if(t<32){
        int h = t>>2, d = t&3;
        float qn = fmaxf(sqrtf(red[128 + h*8 + d]), 1e-12f);
        float tt = temp[h];
        float vals[4]; float m = -3.4e38f;
        #pragma unroll
        for(int e=0;e<4;e++){
            float kn = fmaxf(sqrtf(red[128 + h*8 + 4 + e]), 1e-12f);
            vals[e] = red[h*16 + d*4 + e] / (qn*kn) * tt;
            m = fmaxf(m, vals[e]);
        }
        float s=0.f;
        #pragma unroll
        for(int e=0;e<4;e++){ vals[e]=expf(vals[e]-m); s+=vals[e]; }
        float inv = 1.f/s;
        #pragma unroll
        for(int e=0;e<4;e++) g_attn2[b*128 + h*16 + d*4 + e] = vals[e]*inv;
    }
}

// ---------------- K3: lin finish: 0.5v + q@attn, norm, +dconv, proj -> f1; smem pool epilogue ----------------
__global__ __launch_bounds__(128) void lin_out_kernel(const float* __restrict__ dconv_w,
                                                      const float* __restrict__ projw,
                                                      const float* __restrict__ projb){
    __shared__ float attnS[128];
    __shared__ float w9[72];
    __shared__ ull pw[512];
    __shared__ float pb[32];
    __shared__ float sf[32][133];
    __shared__ float cs[4][32], cm[4][32];
    int tid = threadIdx.x, b = blockIdx.y;
    attnS[tid] = g_attn1[b*128 + tid];
    if(tid<72) w9[tid] = dconv_w[tid];
    if(tid<32) pb[tid] = projb[tid];
    const ull* pwg = (const ull*)projw;
    for(int i=tid;i<512;i+=128) pw[i]=pwg[i];
    __syncthreads();
    int l = blockIdx.x*128 + tid;
    const float* qb = g_q1 + b*CC*LL + l;
    const float* vb = g_v1 + b*CC*LL + l;
    float o[32];
    #pragma unroll
    for(int h=0;h<8;h++){
        float qv[4], vv[4];
        #pragma unroll
        for(int d=0;d<4;d++){ qv[d]=qb[(h*4+d)*LL]; vv[d]=vb[(h*4+d)*LL]; }
        float ov[4]; float s = 0.f;
        #pragma unroll
        for(int e=0;e<4;e++){
            float t = 0.5f*vv[e];
            #pragma unroll
            for(int d=0;d<4;d++) t += qv[d]*attnS[h*16 + d*4 + e];
            ov[e]=t; s += t*t;
        }
        float inv = rsqrtf(s);
        #pragma unroll
        for(int d=0;d<4;d++){
            float acc = 0.f;
            #pragma unroll
            for(int t9=0;t9<9;t9++){
                int ll = l + t9 - 4;
                if(ll>=0 && ll<LL) acc += w9[h*9+t9]*vb[(h*4+d)*LL + (t9-4)];
            }
            o[h*4+d] = ov[d]*inv + acc;
        }
    }
    ull op[16];
    #pragma unroll
    for(int cc=0;cc<16;cc++) op[cc]=pack2(o[2*cc], o[2*cc+1]);
    float* fb = g_f1 + b*CC*LL + l;
    #pragma unroll
    for(int c=0;c<32;c++){
        ull a0=0ULL, a1=0ULL;
        #pragma unroll
        for(int cc=0;cc<16;cc+=2){ fma2(a0,pw[c*16+cc],op[cc]); fma2(a1,pw[c*16+cc+1],op[cc+1]); }
        float f = hsum2(a0)+hsum2(a1)+pb[c];
        fb[c*LL] = f;
        sf[c][tid] = f;
    }
    __syncthreads();
    {
        int c = tid&31, q4 = tid>>5;
        const float* row = sf[c] + q4*32;
        float s = 0.f, m = -3.4e38f;
        #pragma unroll 8
        for(int j=0;j<32;j++){ float v=row[j]; s+=v; m=fmaxf(m,v); }
        cs[q4][c]=s; cm[q4][c]=m;
    }
    __syncthreads();
    if(tid<32){
        int blk = b*50 + blockIdx.x;
        g_poolp[0][blk][tid]    = cs[0][tid]+cs[1][tid]+cs[2][tid]+cs[3][tid];
        g_poolp[0][blk][32+tid] = fmaxf(fmaxf(cm[0][tid],cm[1][tid]),fmaxf(cm[2][tid],cm[3][tid]));
    }
}

// ---------------- K4: XCA finish: attn@v, proj -> f2; smem pool epilogue ----------------
__global__ __launch_bounds__(128) void xca_out_kernel(const float* __restrict__ projw,
                                                      const float* __restrict__ projb){
    __shared__ float attnS[128];
    __shared__ ull pw[512];
    __shared__ float pb[32];
    __shared__ float sf[32][133];
    __shared__ float cs[4][32], cm[4][32];
    int tid = threadIdx.x, b = blockIdx.y;
    attnS[tid] = g_attn2[b*128 + tid];
    if(tid<32) pb[tid] = projb[tid];
    const ull* pwg = (const ull*)projw;
    for(int i=tid;i<512;i+=128) pw[i]=pwg[i];
    __syncthreads();
    int l = blockIdx.x*128 + tid;
    const float* vb = g_v2 + b*CC*LL + l;
    float o[32];
    #pragma unroll
    for(int h=0;h<8;h++){
        float vv[4];
        #pragma unroll
        for(int e=0;e<4;e++) vv[e]=vb[(h*4+e)*LL];
        #pragma unroll
        for(int d=0;d<4;d++){
            float t = 0.f;
            #pragma unroll
            for(int e=0;e<4;e++) t += attnS[h*16 + d*4 + e]*vv[e];
            o[h*4+d]=t;
        }
    }
    ull op[16];
    #pragma unroll
    for(int cc=0;cc<16;cc++) op[cc]=pack2(o[2*cc], o[2*cc+1]);
    float* fb = g_f2 + b*CC*LL + l;
    #pragma unroll
    for(int c=0;c<32;c++){
        ull a0=0ULL, a1=0ULL;
        #pragma unroll
        for(int cc=0;cc<16;cc+=2){ fma2(a0,pw[c*16+cc],op[cc]); fma2(a1,pw[c*16+cc+1],op[cc+1]); }
        float f = hsum2(a0)+hsum2(a1)+pb[c];
        fb[c*LL] = f;
        sf[c][tid] = f;
    }
    __syncthreads();
    {
        int c = tid&31, q4 = tid>>5;
        const float* row = sf[c] + q4*32;
        float s = 0.f, m = -3.4e38f;
        #pragma unroll 8
        for(int j=0;j<32;j++){ float v=row[j]; s+=v; m=fmaxf(m,v); }
        cs[q4][c]=s; cm[q4][c]=m;
    }
    __syncthreads();
    if(tid<32){
        int blk = b*50 + blockIdx.x;
        g_poolp[1][blk][tid]    = cs[0][tid]+cs[1][tid]+cs[2][tid]+cs[3][tid];
        g_poolp[1][blk][32+tid] = fmaxf(fmaxf(cm[0][tid],cm[1][tid]),fmaxf(cm[2][tid],cm[3][tid]));
    }
}

// ---------------- K5: pool reduce ----------------
__global__ __launch_bounds__(64) void pool_red_kernel(){
    int s = blockIdx.x>>6, b = blockIdx.x&63;
    int t = threadIdx.x;
    if(t<32){
        float acc = 0.f;
        #pragma unroll
        for(int i=0;i<50;i++) acc += g_poolp[s][b*50+i][t];
        g_avg[s*BB*CC + b*32 + t] = acc;
    } else {
        int c = t-32;
        float m = -3.4e38f;
        #pragma unroll
        for(int i=0;i<50;i++) m = fmaxf(m, g_poolp[s][b*50+i][32+c]);
        g_mx[s*BB*CC + b*32 + c] = m;
    }
}

// ---------------- K6: CAFM channel MLPs + cross softmax weights ----------------
__global__ __launch_bounds__(64) void cafm_kernel(
    const float* __restrict__ aw1,  const float* __restrict__ ab1,
    const float* __restrict__ mw1,  const float* __restrict__ mb1,
    const float* __restrict__ aw2,  const float* __restrict__ ab2,
    const float* __restrict__ mw2,  const float* __restrict__ mb2,
    const float* __restrict__ aw11, const float* __restrict__ ab11,
    const float* __restrict__ mw11, const float* __restrict__ mb11,
    const float* __restrict__ aw22, const float* __restrict__ ab22,
    const float* __restrict__ mw22, const float* __restrict__ mb22){
    int b = blockIdx.x, t = threadIdx.x;
    __shared__ float sa[4][32], hid[4][16], a1s[32], a2s[32];
    if(t<32){
        sa[0][t] = g_avg[b*32+t] * (1.0f/LL);
        sa[1][t] = g_mx[b*32+t];
        sa[2][t] = g_avg[BB*CC + b*32+t] * (1.0f/LL);
        sa[3][t] = g_mx[BB*CC + b*32+t];
    }
    __syncthreads();
    {
        int br = t>>4, hh = t&15;
        const float* w  = (br==0)?aw1 : (br==1)?mw1 : (br==2)?aw2 : mw2;
        const float* bi = (br==0)?ab1 : (br==1)?mb1 : (br==2)?ab2 : mb2;
        float s = bi[hh];
        #pragma unroll
        for(int c=0;c<32;c++) s += sa[br][c]*w[hh*32+c];
        hid[br][hh] = fmaxf(s, 0.f);
    }
    __syncthreads();
    if(t<32){
        float s = ab11[t] + mb11[t];
        #pragma unroll
        for(int h=0;h<16;h++) s += hid[0][h]*aw11[t*16+h] + hid[1][h]*mw11[t*16+h];
        a1s[t]=s;
    } else {
        int c = t-32;
        float s = ab22[c] + mb22[c];
        #pragma unroll
        for(int h=0;h<16;h++) s += hid[2][h]*aw22[c*16+h] + hid[3][h]*mw22[c*16+h];
        a2s[c]=s;
    }
    __syncthreads();
    if(t<32){
        float a = a1s[t];
        float e[32]; float m = -3.4e38f;
        #pragma unroll
        for(int d=0;d<32;d++){ e[d]=a*a2s[d]; m=fmaxf(m,e[d]); }
        float s=0.f;
        #pragma unroll
        for(int d=0;d<32;d++){ e[d]=expf(e[d]-m); s+=e[d]; }
        float inv = 1.f/s;
        #pragma unroll
        for(int d=0;d<32;d++) g_w1[b*1024 + t*32 + d] = e[d]*inv;
    } else {
        int c = t-32;
        float a = a2s[c];
        float e[32]; float m = -3.4e38f;
        #pragma unroll
        for(int d=0;d<32;d++){ e[d]=a*a1s[d]; m=fmaxf(m,e[d]); }
        float s=0.f;
        #pragma unroll
        for(int d=0;d<32;d++){ e[d]=expf(e[d]-m); s+=e[d]; }
        float inv = 1.f/s;
        #pragma unroll
        for(int d=0;d<32;d++) g_w2[b*1024 + c*32 + d] = e[d]*inv;
    }
}

// ---------------- K7: a1f/a2f matvec + channel mean/max -> g_pool ----------------
__global__ __launch_bounds__(128) void a1f_pool_kernel(){
    __shared__ ull w1s[512], w2s[512];
    int tid = threadIdx.x, b = blockIdx.y;
    const ull* w1g = (const ull*)(g_w1 + b*1024);
    const ull* w2g = (const ull*)(g_w2 + b*1024);
    for(int i=tid;i<512;i+=128){ w1s[i]=w1g[i]; w2s[i]=w2g[i]; }
    __syncthreads();
    int l = blockIdx.x*128 + tid;
    const float* f1b = g_f1 + b*CC*LL + l;
    const float* f2b = g_f2 + b*CC*LL + l;
    ull f1p[16], f2p[16];
    #pragma unroll
    for(int cc=0;cc<16;cc++){
        f1p[cc] = pack2(f1b[(2*cc)*LL], f1b[(2*cc+1)*LL]);
        f2p[cc] = pack2(f2b[(2*cc)*LL], f2b[(2*cc+1)*LL]);
    }
    float s1=0.f, m1=-3.4e38f, s2=0.f, m2=-3.4e38f;
    #pragma unroll
    for(int c=0;c<32;c++){
        ull a0=0ULL,a1=0ULL,b0=0ULL,b1=0ULL;
        #pragma unroll
        for(int cc=0;cc<16;cc+=2){
            fma2(a0,w1s[c*16+cc],f1p[cc]);   fma2(a1,w1s[c*16+cc+1],f1p[cc+1]);
            fma2(b0,w2s[c*16+cc],f2p[cc]);   fma2(b1,w2s[c*16+cc+1],f2p[cc+1]);
        }
        float v1 = hsum2(a0)+hsum2(a1);
        float v2 = hsum2(b0)+hsum2(b1);
        s1+=v1; m1=fmaxf(m1,v1);
        s2+=v2; m2=fmaxf(m2,v2);
    }
    g_pool[(0*BB+b)*LL + l] = s1*(1.f/32.f);
    g_pool[(1*BB+b)*LL + l] = m1;
    g_pool[(2*BB+b)*LL + l] = s2*(1.f/32.f);
    g_pool[(3*BB+b)*LL + l] = m2;
}

// ---------------- K8: spatial gate ----------------
__global__ __launch_bounds__(256) void gate_kernel(const float* __restrict__ c1w,
                                                   const float* __restrict__ c1b,
                                                   const float* __restrict__ c2w,
                                                   const float* __restrict__ c2b){
    __shared__ float y1[LL];
    __shared__ float red[8];
    int t = threadIdx.x;
    int b = blockIdx.x>>1, s = blockIdx.x&1;
    const float* pm = g_pool + ((s*2+0)*BB + b)*LL;
    const float* px = g_pool + ((s*2+1)*BB + b)*LL;
    float w1c[18];
    #pragma unroll
    for(int i=0;i<18;i++) w1c[i]=c1w[i];
    float b1 = c1b[0];
    for(int l=t; l<LL; l+=256){
        int iy = l/80, ix = l%80;
        float acc = b1;
        #pragma unroll
        for(int ky=0;ky<3;ky++){
            int yy = iy+ky-1; if(yy<0||yy>=80) continue;
            #pragma unroll
            for(int kx=0;kx<3;kx++){
                int xx = ix+kx-1; if(xx<0||xx>=80) continue;
                int p = yy*80+xx;
                acc += w1c[ky*3+kx]*pm[p] + w1c[9+ky*3+kx]*px[p];
            }
        }
        y1[l] = fmaxf(acc, 0.f);
    }
    __syncthreads();
    float w2c[9];
    #pragma unroll
    for(int i=0;i<9;i++) w2c[i]=c2w[i];
    float b2 = c2b[0];
    float r[25]; float mx = -3.4e38f;
    #pragma unroll
    for(int i=0;i<25;i++){
        int l = t + i*256;
        int iy = l/80, ix = l%80;
        float acc = b2;
        #pragma unroll
        for(int ky=0;ky<3;ky++){
            int yy = iy+ky-1; if(yy<0||yy>=80) continue;
            #pragma unroll
            for(int kx=0;kx<3;kx++){
                int xx = ix+kx-1; if(xx<0||xx>=80) continue;
                acc += w2c[ky*3+kx]*y1[yy*80+xx];
            }
        }
        r[i]=acc; mx=fmaxf(mx,acc);
    }
    int lane = t&31, wid = t>>5;
    #pragma unroll
    for(int o=16;o>0;o>>=1) mx = fmaxf(mx, __shfl_xor_sync(0xffffffffu,mx,o));
    if(lane==0) red[wid]=mx;
    __syncthreads();
    if(t==0){ float m=red[0]; for(int w=1;w<8;w++) m=fmaxf(m,red[w]); red[0]=m; }
    __syncthreads();
    float m = red[0];
    __syncthreads();
    float sm = 0.f;
    #pragma unroll
    for(int i=0;i<25;i++){ r[i]=expf(r[i]-m); sm+=r[i]; }
    #pragma unroll
    for(int o=16;o>0;o>>=1) sm += __shfl_xor_sync(0xffffffffu,sm,o);
    if(lane==0) red[wid]=sm;
    __syncthreads();
    if(t==0){ float a=0.f; for(int w=0;w<8;w++) a+=red[w]; red[0]=a; }
    __syncthreads();
    float inv = 1.f/red[0];
    #pragma unroll
    for(int i=0;i<25;i++) g_gate[(b*2+s)*LL + t + i*256] = r[i]*inv;
}

// ---------------- K9: out = f1*(1+g1) + f2*(1+g2) ----------------
__global__ __launch_bounds__(256) void final_kernel(float* __restrict__ out){
    int i = blockIdx.x*256 + threadIdx.x;
    int idx = i*4;
    int b = idx/(CC*LL);
    int l = idx%LL;
    float4 a  = ((const float4*)g_f1)[i];
    float4 c  = ((const float4*)g_f2)[i];
    float4 g1 = *(const float4*)&g_gate[(b*2+0)*LL + l];
    float4 g2 = *(const float4*)&g_gate[(b*2+1)*LL + l];
    float4 o;
    o.x = a.x*(1.f+g1.x) + c.x*(1.f+g2.x);
    o.y = a.y*(1.f+g1.y) + c.y*(1.f+g2.y);
    o.z = a.z*(1.f+g1.z) + c.z*(1.f+g2.z);
    o.w = a.w*(1.f+g1.w) + c.w*(1.f+g2.w);
    ((float4*)out)[i] = o;
}

// ---------------- launch ----------------
extern "C" void kernel_launch(void* const* d_in, const int* in_sizes, int n_in,
                              void* d_out, int out_size){
    const float* rgb       = (const float*)d_in[0];
    const float* freq      = (const float*)d_in[1];
    const float* la_qkv_w  = (const float*)d_in[2];
    const float* la_proj_w = (const float*)d_in[3];
    const float* la_proj_b = (const float*)d_in[4];
    const float* la_dconv_w= (const float*)d_in[5];
    const float* xa_qkv_w  = (const float*)d_in[6];
    const float* xa_temp   = (const float*)d_in[7];
    const float* xa_proj_w = (const float*)d_in[8];
    const float* xa_proj_b = (const float*)d_in[9];
    const float* c1s_w     = (const float*)d_in[10];
    const float* c1s_b     = (const float*)d_in[11];
    const float* c2s_w     = (const float*)d_in[12];
    const float* c2s_b     = (const float*)d_in[13];

    dim3 g50(50, BB);
    qkv_lin_kernel<<<g50,128>>>(rgb,  la_qkv_w);
    qkv_xca_kernel<<<g50,128>>>(freq, xa_qkv_w);
    lin_red_kernel<<<BB,128>>>();
    xca_red_kernel<<<BB,256>>>(xa_temp);
    lin_out_kernel<<<g50,128>>>(la_dconv_w, la_proj_w, la_proj_b);
    xca_out_kernel<<<g50,128>>>(xa_proj_w, xa_proj_b);
    pool_red_kernel<<<2*BB,64>>>();
    cafm_kernel<<<BB,64>>>((const float*)d_in[14],(const float*)d_in[15],
                           (const float*)d_in[16],(const float*)d_in[17],
                           (const float*)d_in[18],(const float*)d_in[19],
                           (const float*)d_in[20],(const float*)d_in[21],
                           (const float*)d_in[22],(const float*)d_in[23],
                           (const float*)d_in[24],(const float*)d_in[25],
                           (const float*)d_in[26],(const float*)d_in[27],
                           (const float*)d_in[28],(const float*)d_in[29]);
    a1f_pool_kernel<<<g50,128>>>();
    gate_kernel<<<2*BB,256>>>(c1s_w, c1s_b, c2s_w, c2s_b);
    final_kernel<<<(BB*CC*LL/4)/256,256>>>((float*)d_out);
}

// round 6
// speedup vs baseline: 3.7978x; 1.1521x over previous
#include <cuda_runtime.h>
#include <math.h>

#define BB 64
#define CC 32
#define LL 6400
#define NH 8
#define INV_PI 0.318309886183790671538f

typedef unsigned long long ull;

// ---------------- f32x2 packed-math helpers ----------------
__device__ __forceinline__ ull pack2(float lo, float hi){
    ull r; asm("mov.b64 %0,{%1,%2};" : "=l"(r) : "f"(lo), "f"(hi)); return r;
}
__device__ __forceinline__ void fma2(ull& d, ull a, ull b){
    asm("fma.rn.f32x2 %0,%1,%2,%0;" : "+l"(d) : "l"(a), "l"(b));
}
__device__ __forceinline__ float hsum2(ull v){
    float lo, hi; asm("mov.b64 {%0,%1},%2;" : "=f"(lo), "=f"(hi) : "l"(v)); return lo + hi;
}
// 32-term dot: weight row as 8x LDS.128 (ulonglong2), x as 16 packed regs
__device__ __forceinline__ float dot16q(const ulonglong2* w8, const ull* xp){
    ull a0 = 0ULL, a1 = 0ULL;
    #pragma unroll
    for(int i=0;i<8;i++){
        ulonglong2 w = w8[i];
        fma2(a0, w.x, xp[2*i]);
        fma2(a1, w.y, xp[2*i+1]);
    }
    return hsum2(a0) + hsum2(a1);
}

// ---------------- scratch ----------------
__device__ float g_q1[BB*CC*LL];
__device__ float g_v1[BB*CC*LL];
__device__ float g_v2[BB*CC*LL];
__device__ float g_f1[BB*CC*LL];
__device__ float g_f2[BB*CC*LL];
__device__ float g_part1[BB*50*128];
__device__ float g_part2[BB*50*192];
__device__ float g_attn1[BB*NH*16];
__device__ float g_attn2[BB*NH*16];
__device__ float g_poolp[2][BB*50][64];  // [stream][block][c=sum | 32+c=max]
__device__ float g_w1[BB*CC*CC];
__device__ float g_w2[BB*CC*CC];
__device__ float g_pool[4*BB*LL];
__device__ float g_gate[BB*2*LL];

// ---------------- K1: fused qkv (z=0 lin, z=1 xca) + smem epilogue partials ----------------
__global__ __launch_bounds__(128) void qkv_kernel(const float* __restrict__ rgb,
                                                  const float* __restrict__ freq,
                                                  const float* __restrict__ lw,
                                                  const float* __restrict__ xw){
    __shared__ ulonglong2 sw2[768];          // 96 rows x 8 (12KB)
    __shared__ float tA[32][133];
    __shared__ float tB[32][133];
    int tid = threadIdx.x, b = blockIdx.y, S = blockIdx.z;
    const float* x = S ? freq : rgb;
    const ulonglong2* wg = (const ulonglong2*)(S ? xw : lw);
    for(int i=tid; i<768; i+=128) sw2[i] = wg[i];
    __syncthreads();
    int l = blockIdx.x*128 + tid;
    const float* xb = x + b*CC*LL + l;
    ull xp[16];
    #pragma unroll
    for(int c=0;c<16;c++) xp[c] = pack2(xb[(2*c)*LL], xb[(2*c+1)*LL]);

    if(S==0){
        float* qb = g_q1 + b*CC*LL + l;
        float* vb = g_v1 + b*CC*LL + l;
        #pragma unroll
        for(int h=0;h<NH;h++){
            float qv[4], kv[4], vv[4];
            #pragma unroll
            for(int d=0;d<4;d++){
                int j = h*4+d;
                qv[d] = dot16q(sw2 + j*8,        xp);
                kv[d] = dot16q(sw2 + (32+j)*8,   xp);
                vv[d] = dot16q(sw2 + (64+j)*8,   xp);
            }
            float iq = rsqrtf(qv[0]*qv[0]+qv[1]*qv[1]+qv[2]*qv[2]+qv[3]*qv[3]);
            float ik = rsqrtf(kv[0]*kv[0]+kv[1]*kv[1]+kv[2]*kv[2]+kv[3]*kv[3]);
            #pragma unroll
            for(int d=0;d<4;d++){
                qb[(h*4+d)*LL] = qv[d]*iq;
                vb[(h*4+d)*LL] = vv[d];
                tA[h*4+d][tid] = kv[d]*ik;
                tB[h*4+d][tid] = vv[d];
            }
        }
        __syncthreads();
        int h = tid>>4, d = (tid>>2)&3, e = tid&3;
        const float* kr = tA[h*4+d];
        const float* vr = tB[h*4+e];
        float p = 0.f;
        #pragma unroll 8
        for(int i=0;i<128;i++) p += kr[i]*vr[i];
        g_part1[(b*50+blockIdx.x)*128 + tid] = p;
    } else {
        float* vb = g_v2 + b*CC*LL + l;
        #pragma unroll
        for(int h=0;h<NH;h++){
            #pragma unroll
            for(int d=0;d<4;d++){
                int j = h*4+d;
                tA[j][tid] = dot16q(sw2 + j*8,      xp);
                tB[j][tid] = dot16q(sw2 + (32+j)*8, xp);
                vb[j*LL]   = dot16q(sw2 + (64+j)*8, xp);
            }
        }
        __syncthreads();
        float* pout = &g_part2[(b*50+blockIdx.x)*192];
        {
            int h = tid>>4, d = (tid>>2)&3, e = tid&3;
            const float* qr = tA[h*4+d];
            const float* kr = tB[h*4+e];
            float p = 0.f;
            #pragma unroll 8
            for(int i=0;i<128;i++) p += qr[i]*kr[i];
            pout[tid] = p;
        }
        if(tid < 64){
            int h = tid>>3, which = (tid>>2)&1, d = tid&3;
            const float* r = which ? tB[h*4+d] : tA[h*4+d];
            float p = 0.f;
            #pragma unroll 8
            for(int i=0;i<128;i++) p += r[i]*r[i];
            pout[128 + tid] = p;
        }
    }
}

// ---------------- K2: fused reductions (y=0: lin attn, y=1: xca softmax) ----------------
__global__ __launch_bounds__(256) void red_kernel(const float* __restrict__ temp){
    int b = blockIdx.x, t = threadIdx.x;
    if(blockIdx.y==0){
        if(t<128){
            float s = 0.f;
            #pragma unroll
            for(int i=0;i<50;i++) s += g_part1[(b*50+i)*128 + t];
            g_attn1[b*128+t] = INV_PI*s;
        }
        return;
    }
    __shared__ float red[192];
    if(t<192){
        float s=0.f;
        #pragma unroll
        for(int i=0;i<50;i++) s += g_part2[(b*50+i)*192 + t];
        red[t]=s;
    }
    __syncthreads();
    if(t<32){
        int h = t>>2, d = t&3;
        float qn = fmaxf(sqrtf(red[128 + h*8 + d]), 1e-12f);
        float tt = temp[h];
        float vals[4]; float m = -3.4e38f;
        #pragma unroll
        for(int e=0;e<4;e++){
            float kn = fmaxf(sqrtf(red[128 + h*8 + 4 + e]), 1e-12f);
            vals[e] = red[h*16 + d*4 + e] / (qn*kn) * tt;
            m = fmaxf(m, vals[e]);
        }
        float s=0.f;
        #pragma unroll
        for(int e=0;e<4;e++){ vals[e]=expf(vals[e]-m); s+=vals[e]; }
        float inv = 1.f/s;
        #pragma unroll
        for(int e=0;e<4;e++) g_attn2[b*128 + h*16 + d*4 + e] = vals[e]*inv;
    }
}

// ---------------- K3: lin finish (v staged in smem halo tile) + pool epilogue ----------------
__global__ __launch_bounds__(128) void lin_out_kernel(const float* __restrict__ dconv_w,
                                                      const float* __restrict__ projw,
                                                      const float* __restrict__ projb){
    __shared__ float attnS[128];
    __shared__ float w9[72];
    __shared__ ulonglong2 pw2[256];
    __shared__ float pb[32];
    __shared__ float svt[32][136];           // halo tile: cols 0..3 left, 4..131 body, 132..135 right
    __shared__ float sf[32][133];
    __shared__ float cs[4][32], cm[4][32];
    int tid = threadIdx.x, b = blockIdx.y;
    attnS[tid] = g_attn1[b*128 + tid];
    if(tid<72) w9[tid] = dconv_w[tid];
    if(tid<32) pb[tid] = projb[tid];
    const ulonglong2* pwg = (const ulonglong2*)projw;
    for(int i=tid;i<256;i+=128) pw2[i]=pwg[i];
    int base = blockIdx.x*128;
    int l = base + tid;
    const float* vbase = g_v1 + b*CC*LL;
    #pragma unroll
    for(int c=0;c<32;c++) svt[c][4+tid] = vbase[c*LL + l];
    if(tid<8){
        int col = (tid<4) ? tid : (128+tid);
        int hl  = (tid<4) ? (base-4+tid) : (base+128+(tid-4));
        bool ok = (hl>=0 && hl<LL);
        #pragma unroll
        for(int c=0;c<32;c++) svt[c][col] = ok ? vbase[c*LL+hl] : 0.f;
    }
    __syncthreads();
    const float* qb = g_q1 + b*CC*LL + l;
    float o[32];
    #pragma unroll
    for(int h=0;h<8;h++){
        float qv[4], vv[4];
        #pragma unroll
        for(int d=0;d<4;d++){ qv[d]=qb[(h*4+d)*LL]; vv[d]=svt[h*4+d][4+tid]; }
        float ov[4]; float s = 0.f;
        #pragma unroll
        for(int e=0;e<4;e++){
            float t = 0.5f*vv[e];
            #pragma unroll
            for(int d=0;d<4;d++) t += qv[d]*attnS[h*16 + d*4 + e];
            ov[e]=t; s += t*t;
        }
        float inv = rsqrtf(s);
        #pragma unroll
        for(int d=0;d<4;d++){
            float acc = 0.f;
            #pragma unroll
            for(int t9=0;t9<9;t9++) acc += w9[h*9+t9]*svt[h*4+d][tid+t9];
            o[h*4+d] = ov[d]*inv + acc;
        }
    }
    ull op[16];
    #pragma unroll
    for(int cc=0;cc<16;cc++) op[cc]=pack2(o[2*cc], o[2*cc+1]);
    float* fb = g_f1 + b*CC*LL + l;
    #pragma unroll
    for(int c=0;c<32;c++){
        ull a0=0ULL, a1=0ULL;
        #pragma unroll
        for(int i=0;i<8;i++){
            ulonglong2 w = pw2[c*8+i];
            fma2(a0,w.x,op[2*i]); fma2(a1,w.y,op[2*i+1]);
        }
        float f = hsum2(a0)+hsum2(a1)+pb[c];
        fb[c*LL] = f;
        sf[c][tid] = f;
    }
    __syncthreads();
    {
        int c = tid&31, q4 = tid>>5;
        const float* row = sf[c] + q4*32;
        float s = 0.f, m = -3.4e38f;
        #pragma unroll 8
        for(int j=0;j<32;j++){ float v=row[j]; s+=v; m=fmaxf(m,v); }
        cs[q4][c]=s; cm[q4][c]=m;
    }
    __syncthreads();
    if(tid<32){
        int blk = b*50 + blockIdx.x;
        g_poolp[0][blk][tid]    = cs[0][tid]+cs[1][tid]+cs[2][tid]+cs[3][tid];
        g_poolp[0][blk][32+tid] = fmaxf(fmaxf(cm[0][tid],cm[1][tid]),fmaxf(cm[2][tid],cm[3][tid]));
    }
}

// ---------------- K4: XCA finish + pool epilogue ----------------
__global__ __launch_bounds__(128) void xca_out_kernel(const float* __restrict__ projw,
                                                      const float* __restrict__ projb){
    __shared__ float attnS[128];
    __shared__ ulonglong2 pw2[256];
    __shared__ float pb[32];
    __shared__ float sf[32][133];
    __shared__ float cs[4][32], cm[4][32];
    int tid = threadIdx.x, b = blockIdx.y;
    attnS[tid] = g_attn2[b*128 + tid];
    if(tid<32) pb[tid] = projb[tid];
    const ulonglong2* pwg = (const ulonglong2*)projw;
    for(int i=tid;i<256;i+=128) pw2[i]=pwg[i];
    __syncthreads();
    int l = blockIdx.x*128 + tid;
    const float* vb = g_v2 + b*CC*LL + l;
    float o[32];
    #pragma unroll
    for(int h=0;h<8;h++){
        float vv[4];
        #pragma unroll
        for(int e=0;e<4;e++) vv[e]=vb[(h*4+e)*LL];
        #pragma unroll
        for(int d=0;d<4;d++){
            float t = 0.f;
            #pragma unroll
            for(int e=0;e<4;e++) t += attnS[h*16 + d*4 + e]*vv[e];
            o[h*4+d]=t;
        }
    }
    ull op[16];
    #pragma unroll
    for(int cc=0;cc<16;cc++) op[cc]=pack2(o[2*cc], o[2*cc+1]);
    float* fb = g_f2 + b*CC*LL + l;
    #pragma unroll
    for(int c=0;c<32;c++){
        ull a0=0ULL, a1=0ULL;
        #pragma unroll
        for(int i=0;i<8;i++){
            ulonglong2 w = pw2[c*8+i];
            fma2(a0,w.x,op[2*i]); fma2(a1,w.y,op[2*i+1]);
        }
        float f = hsum2(a0)+hsum2(a1)+pb[c];
        fb[c*LL] = f;
        sf[c][tid] = f;
    }
    __syncthreads();
    {
        int c = tid&31, q4 = tid>>5;
        const float* row = sf[c] + q4*32;
        float s = 0.f, m = -3.4e38f;
        #pragma unroll 8
        for(int j=0;j<32;j++){ float v=row[j]; s+=v; m=fmaxf(m,v); }
        cs[q4][c]=s; cm[q4][c]=m;
    }
    __syncthreads();
    if(tid<32){
        int blk = b*50 + blockIdx.x;
        g_poolp[1][blk][tid]    = cs[0][tid]+cs[1][tid]+cs[2][tid]+cs[3][tid];
        g_poolp[1][blk][32+tid] = fmaxf(fmaxf(cm[0][tid],cm[1][tid]),fmaxf(cm[2][tid],cm[3][tid]));
    }
}

// ---------------- K5: CAFM (pool reduce folded in) ----------------
__global__ __launch_bounds__(64) void cafm_kernel(
    const float* __restrict__ aw1,  const float* __restrict__ ab1,
    const float* __restrict__ mw1,  const float* __restrict__ mb1,
    const float* __restrict__ aw2,  const float* __restrict__ ab2,
    const float* __restrict__ mw2,  const float* __restrict__ mb2,
    const float* __restrict__ aw11, const float* __restrict__ ab11,
    const float* __restrict__ mw11, const float* __restrict__ mb11,
    const float* __restrict__ aw22, const float* __restrict__ ab22,
    const float* __restrict__ mw22, const float* __restrict__ mb22){
    int b = blockIdx.x, t = threadIdx.x;
    __shared__ float sa[4][32], hid[4][16], a1s[32], a2s[32];
    if(t<32){
        float s1=0.f, m1=-3.4e38f, s2=0.f, m2=-3.4e38f;
        #pragma unroll
        for(int i=0;i<50;i++){
            s1 += g_poolp[0][b*50+i][t];
            m1 = fmaxf(m1, g_poolp[0][b*50+i][32+t]);
            s2 += g_poolp[1][b*50+i][t];
            m2 = fmaxf(m2, g_poolp[1][b*50+i][32+t]);
        }
        sa[0][t] = s1 * (1.0f/LL);
        sa[1][t] = m1;
        sa[2][t] = s2 * (1.0f/LL);
        sa[3][t] = m2;
    }
    __syncthreads();
    {
        int br = t>>4, hh = t&15;
        const float* w  = (br==0)?aw1 : (br==1)?mw1 : (br==2)?aw2 : mw2;
        const float* bi = (br==0)?ab1 : (br==1)?mb1 : (br==2)?ab2 : mb2;
        float s = bi[hh];
        #pragma unroll
        for(int c=0;c<32;c++) s += sa[br][c]*w[hh*32+c];
        hid[br][hh] = fmaxf(s, 0.f);
    }
    __syncthreads();
    if(t<32){
        float s = ab11[t] + mb11[t];
        #pragma unroll
        for(int h=0;h<16;h++) s += hid[0][h]*aw11[t*16+h] + hid[1][h]*mw11[t*16+h];
        a1s[t]=s;
    } else {
        int c = t-32;
        float s = ab22[c] + mb22[c];
        #pragma unroll
        for(int h=0;h<16;h++) s += hid[2][h]*aw22[c*16+h] + hid[3][h]*mw22[c*16+h];
        a2s[c]=s;
    }
    __syncthreads();
    if(t<32){
        float a = a1s[t];
        float e[32]; float m = -3.4e38f;
        #pragma unroll
        for(int d=0;d<32;d++){ e[d]=a*a2s[d]; m=fmaxf(m,e[d]); }
        float s=0.f;
        #pragma unroll
        for(int d=0;d<32;d++){ e[d]=expf(e[d]-m); s+=e[d]; }
        float inv = 1.f/s;
        #pragma unroll
        for(int d=0;d<32;d++) g_w1[b*1024 + t*32 + d] = e[d]*inv;
    } else {
        int c = t-32;
        float a = a2s[c];
        float e[32]; float m = -3.4e38f;
        #pragma unroll
        for(int d=0;d<32;d++){ e[d]=a*a1s[d]; m=fmaxf(m,e[d]); }
        float s=0.f;
        #pragma unroll
        for(int d=0;d<32;d++){ e[d]=expf(e[d]-m); s+=e[d]; }
        float inv = 1.f/s;
        #pragma unroll
        for(int d=0;d<32;d++) g_w2[b*1024 + c*32 + d] = e[d]*inv;
    }
}

// ---------------- K6: a1f/a2f matvec + channel mean/max -> g_pool ----------------
__global__ __launch_bounds__(128) void a1f_pool_kernel(){
    __shared__ ulonglong2 w1s[256], w2s[256];
    int tid = threadIdx.x, b = blockIdx.y;
    const ulonglong2* w1g = (const ulonglong2*)(g_w1 + b*1024);
    const ulonglong2* w2g = (const ulonglong2*)(g_w2 + b*1024);
    for(int i=tid;i<256;i+=128){ w1s[i]=w1g[i]; w2s[i]=w2g[i]; }
    __syncthreads();
    int l = blockIdx.x*128 + tid;
    const float* f1b = g_f1 + b*CC*LL + l;
    const float* f2b = g_f2 + b*CC*LL + l;
    ull f1p[16], f2p[16];
    #pragma unroll
    for(int cc=0;cc<16;cc++){
        f1p[cc] = pack2(f1b[(2*cc)*LL], f1b[(2*cc+1)*LL]);
        f2p[cc] = pack2(f2b[(2*cc)*LL], f2b[(2*cc+1)*LL]);
    }
    float s1=0.f, m1=-3.4e38f, s2=0.f, m2=-3.4e38f;
    #pragma unroll
    for(int c=0;c<32;c++){
        ull a0=0ULL,a1=0ULL,b0=0ULL,b1=0ULL;
        #pragma unroll
        for(int i=0;i<8;i++){
            ulonglong2 w1 = w1s[c*8+i];
            ulonglong2 w2 = w2s[c*8+i];
            fma2(a0,w1.x,f1p[2*i]); fma2(a1,w1.y,f1p[2*i+1]);
            fma2(b0,w2.x,f2p[2*i]); fma2(b1,w2.y,f2p[2*i+1]);
        }
        float v1 = hsum2(a0)+hsum2(a1);
        float v2 = hsum2(b0)+hsum2(b1);
        s1+=v1; m1=fmaxf(m1,v1);
        s2+=v2; m2=fmaxf(m2,v2);
    }
    g_pool[(0*BB+b)*LL + l] = s1*(1.f/32.f);
    g_pool[(1*BB+b)*LL + l] = m1;
    g_pool[(2*BB+b)*LL + l] = s2*(1.f/32.f);
    g_pool[(3*BB+b)*LL + l] = m2;
}

// ---------------- K7: spatial gate ----------------
__global__ __launch_bounds__(256) void gate_kernel(const float* __restrict__ c1w,
                                                   const float* __restrict__ c1b,
                                                   const float* __restrict__ c2w,
                                                   const float* __restrict__ c2b){
    __shared__ float y1[LL];
    __shared__ float red[8];
    int t = threadIdx.x;
    int b = blockIdx.x>>1, s = blockIdx.x&1;
    const float* pm = g_pool + ((s*2+0)*BB + b)*LL;
    const float* px = g_pool + ((s*2+1)*BB + b)*LL;
    float w1c[18];
    #pragma unroll
    for(int i=0;i<18;i++) w1c[i]=c1w[i];
    float b1 = c1b[0];
    for(int l=t; l<LL; l+=256){
        int iy = l/80, ix = l%80;
        float acc = b1;
        #pragma unroll
        for(int ky=0;ky<3;ky++){
            int yy = iy+ky-1; if(yy<0||yy>=80) continue;
            #pragma unroll
            for(int kx=0;kx<3;kx++){
                int xx = ix+kx-1; if(xx<0||xx>=80) continue;
                int p = yy*80+xx;
                acc += w1c[ky*3+kx]*pm[p] + w1c[9+ky*3+kx]*px[p];
            }
        }
        y1[l] = fmaxf(acc, 0.f);
    }
    __syncthreads();
    float w2c[9];
    #pragma unroll
    for(int i=0;i<9;i++) w2c[i]=c2w[i];
    float b2 = c2b[0];
    float r[25]; float mx = -3.4e38f;
    #pragma unroll
    for(int i=0;i<25;i++){
        int l = t + i*256;
        int iy = l/80, ix = l%80;
        float acc = b2;
        #pragma unroll
        for(int ky=0;ky<3;ky++){
            int yy = iy+ky-1; if(yy<0||yy>=80) continue;
            #pragma unroll
            for(int kx=0;kx<3;kx++){
                int xx = ix+kx-1; if(xx<0||xx>=80) continue;
                acc += w2c[ky*3+kx]*y1[yy*80+xx];
            }
        }
        r[i]=acc; mx=fmaxf(mx,acc);
    }
    int lane = t&31, wid = t>>5;
    #pragma unroll
    for(int o=16;o>0;o>>=1) mx = fmaxf(mx, __shfl_xor_sync(0xffffffffu,mx,o));
    if(lane==0) red[wid]=mx;
    __syncthreads();
    if(t==0){ float m=red[0]; for(int w=1;w<8;w++) m=fmaxf(m,red[w]); red[0]=m; }
    __syncthreads();
    float m = red[0];
    __syncthreads();
    float sm = 0.f;
    #pragma unroll
    for(int i=0;i<25;i++){ r[i]=expf(r[i]-m); sm+=r[i]; }
    #pragma unroll
    for(int o=16;o>0;o>>=1) sm += __shfl_xor_sync(0xffffffffu,sm,o);
    if(lane==0) red[wid]=sm;
    __syncthreads();
    if(t==0){ float a=0.f; for(int w=0;w<8;w++) a+=red[w]; red[0]=a; }
    __syncthreads();
    float inv = 1.f/red[0];
    #pragma unroll
    for(int i=0;i<25;i++) g_gate[(b*2+s)*LL + t + i*256] = r[i]*inv;
}

// ---------------- K8: out = f1*(1+g1) + f2*(1+g2) ----------------
__global__ __launch_bounds__(256) void final_kernel(float* __restrict__ out){
    int i = blockIdx.x*256 + threadIdx.x;
    int idx = i*4;
    int b = idx/(CC*LL);
    int l = idx%LL;
    float4 a  = ((const float4*)g_f1)[i];
    float4 c  = ((const float4*)g_f2)[i];
    float4 g1 = *(const float4*)&g_gate[(b*2+0)*LL + l];
    float4 g2 = *(const float4*)&g_gate[(b*2+1)*LL + l];
    float4 o;
    o.x = a.x*(1.f+g1.x) + c.x*(1.f+g2.x);
    o.y = a.y*(1.f+g1.y) + c.y*(1.f+g2.y);
    o.z = a.z*(1.f+g1.z) + c.z*(1.f+g2.z);
    o.w = a.w*(1.f+g1.w) + c.w*(1.f+g2.w);
    ((float4*)out)[i] = o;
}

// ---------------- launch ----------------
extern "C" void kernel_launch(void* const* d_in, const int* in_sizes, int n_in,
                              void* d_out, int out_size){
    const float* rgb       = (const float*)d_in[0];
    const float* freq      = (const float*)d_in[1];
    const float* la_qkv_w  = (const float*)d_in[2];
    const float* la_proj_w = (const float*)d_in[3];
    const float* la_proj_b = (const float*)d_in[4];
    const float* la_dconv_w= (const float*)d_in[5];
    const float* xa_qkv_w  = (const float*)d_in[6];
    const float* xa_temp   = (const float*)d_in[7];
    const float* xa_proj_w = (const float*)d_in[8];
    const float* xa_proj_b = (const float*)d_in[9];
    const float* c1s_w     = (const float*)d_in[10];
    const float* c1s_b     = (const float*)d_in[11];
    const float* c2s_w     = (const float*)d_in[12];
    const float* c2s_b     = (const float*)d_in[13];

    dim3 gqkv(50, BB, 2), g50(50, BB), gred(BB, 2);
    qkv_kernel<<<gqkv,128>>>(rgb, freq, la_qkv_w, xa_qkv_w);
    red_kernel<<<gred,256>>>(xa_temp);
    lin_out_kernel<<<g50,128>>>(la_dconv_w, la_proj_w, la_proj_b);
    xca_out_kernel<<<g50,128>>>(xa_proj_w, xa_proj_b);
    cafm_kernel<<<BB,64>>>((const float*)d_in[14],(const float*)d_in[15],
                           (const float*)d_in[16],(const float*)d_in[17],
                           (const float*)d_in[18],(const float*)d_in[19],
                           (const float*)d_in[20],(const float*)d_in[21],
                           (const float*)d_in[22],(const float*)d_in[23],
                           (const float*)d_in[24],(const float*)d_in[25],
                           (const float*)d_in[26],(const float*)d_in[27],
                           (const float*)d_in[28],(const float*)d_in[29]);
    a1f_pool_kernel<<<g50,128>>>();
    gate_kernel<<<2*BB,256>>>(c1s_w, c1s_b, c2s_w, c2s_b);
    final_kernel<<<(BB*CC*LL/4)/256,256>>>((float*)d_out);
}